// round 8
// baseline (speedup 1.0000x reference)
#include <cuda_runtime.h>
#include <math.h>
#include <stdint.h>

#define TOKENS 2048
#define HDIM   2048
#define H2DIM  1024
#define NE     16
#define NMOD   4
#define CAP    768
#define KD     2048

static constexpr long long C_OFF   = (long long)TOKENS * NE * CAP;
static constexpr long long RP_OFF  = 2 * C_OFF;
static constexpr long long AUX_OFF = RP_OFF + (long long)TOKENS * NE;

// ---------------- device scratch ---------------------------------------------
__device__ float g_T1 [TOKENS * HDIM];
__device__ float g_T1g[TOKENS * HDIM];
__device__ float g_T2 [TOKENS * HDIM];
__device__ float g_S1 [NMOD * TOKENS * H2DIM];
__device__ float g_glog[TOKENS * NE];
__device__ float g_slog[NMOD * TOKENS * NE];
__device__ float g_partial[8 * NE];

struct GemmBatch {
    const float* A[4];
    const float* B[4];
    const float* bias[4];
    float*       C[4];
};
struct LogitsBatch {
    const float* X[5];
    const float* W[5];
    const float* bias[5];
    float*       out[5];
    int          Kd[5];
};

// ---------------- helpers ------------------------------------------------------
__device__ __forceinline__ void split2(float v, uint32_t& hb, uint32_t& lb) {
    asm("cvt.rna.tf32.f32 %0, %1;" : "=r"(hb) : "f"(v));
    float lo = v - __uint_as_float(hb);
    asm("cvt.rna.tf32.f32 %0, %1;" : "=r"(lb) : "f"(lo));
}

__device__ __forceinline__ void mma_tf32(float* c, const uint32_t* a, const uint32_t* b) {
    asm volatile(
        "mma.sync.aligned.m16n8k8.row.col.f32.tf32.tf32.f32 "
        "{%0,%1,%2,%3}, {%4,%5,%6,%7}, {%8,%9}, {%0,%1,%2,%3};"
        : "+f"(c[0]), "+f"(c[1]), "+f"(c[2]), "+f"(c[3])
        : "r"(a[0]), "r"(a[1]), "r"(a[2]), "r"(a[3]), "r"(b[0]), "r"(b[1]));
}

// ---------------- zero-fill -----------------------------------------------------
__global__ void zero_kernel(float4* __restrict__ p, int n4) {
    int i = blockIdx.x * blockDim.x + threadIdx.x;
    int stride = gridDim.x * blockDim.x;
    float4 z = make_float4(0.f, 0.f, 0.f, 0.f);
    for (; i < n4; i += stride) p[i] = z;
}

// ---------------- HMMA 3xTF32 GEMM, fragment-major smem, double-buffered -------
// C[M,N] = act(A[M,2048] @ W[2048,N] + bias). 128x128 CTA tile, BK=32,
// 256 threads (8 warps, 64x32 warp tiles). In-kernel tf32 hi/lo split.
//
// Smem per stage (uint32 words), fragment-major:
//   Ah quads [kc 0..3][mb 0..7][lane][4]   = 4096 words (off 0)
//   Al quads                                = 4096 words (off 4096)
//   Bh pairs [kc 0..3][nb 0..15][lane][2]  = 4096 words (off 8192)
//   Bl pairs                                = 4096 words (off 12288)
// A quad = {A(r,t), A(r+8,t), A(r,t+4), A(r+8,t+4)}, r=mb*16+gid, t=kc*8+tig.
// B pair = {W(t,n), W(t+4,n)},                       n=nb*8+gid,  t=kc*8+tig.
#define STG_W  16384
#define SMEM_BYTES (2 * STG_W * 4)   // 131072

__global__ __launch_bounds__(256) void gemm_hmma_b(
    GemmBatch gb, int N, int do_relu)
{
    extern __shared__ uint32_t sm[];

    const int z    = blockIdx.z;
    const float* __restrict__ A    = gb.A[z];
    const float* __restrict__ W    = gb.B[z];
    const float* __restrict__ bias = gb.bias[z];
    float* __restrict__ C          = gb.C[z];

    const int tid  = threadIdx.x;
    const int wid  = tid >> 5;
    const int lane = tid & 31;
    const int gid  = lane >> 2;
    const int tig  = lane & 3;
    const int ambase = (wid & 1) * 4;
    const int nbbase = (wid >> 1) * 4;
    const int wm   = (wid & 1) * 64;
    const int wn   = (wid >> 1) * 32;
    const int bm   = blockIdx.y * 128;
    const int bn   = blockIdx.x * 128;

    // global gather pointers (thread owns mb=wid for A; nb={wid,wid+8} for B)
    const float* ar0 = A + (size_t)(bm + wid * 16 + gid) * KD + tig;
    const float* ar1 = ar0 + (size_t)8 * KD;
    const float* bc0 = W + (size_t)tig * N + bn + wid * 8 + gid;   // k includes tig
    const float* bc1 = bc0 + 64;                                   // nb + 8 -> +64 cols

    float acc[4][4][4];
#pragma unroll
    for (int mt = 0; mt < 4; mt++)
#pragma unroll
        for (int nt = 0; nt < 4; nt++)
#pragma unroll
            for (int r = 0; r < 4; r++) acc[mt][nt][r] = 0.f;

    float a_pf[16], b_pf[16];
    // preload kb = 0
#pragma unroll
    for (int i = 0; i < 4; i++) {
        int kk = i * 8;
        a_pf[4*i+0] = ar0[kk];
        a_pf[4*i+1] = ar1[kk];
        a_pf[4*i+2] = ar0[kk + 4];
        a_pf[4*i+3] = ar1[kk + 4];
    }
#pragma unroll
    for (int i = 0; i < 8; i++) {
        int kc = i >> 1;
        const float* p = ((i & 1) ? bc1 : bc0) + (size_t)(kc * 8) * N;
        b_pf[2*i]   = p[0];
        b_pf[2*i+1] = p[(size_t)4 * N];
    }

    for (int kb = 0; kb < KD / 32; kb++) {
        uint32_t* st = sm + (kb & 1) * STG_W;

        // ---- split + store fragment-major (conflict-free) ----
#pragma unroll
        for (int i = 0; i < 4; i++) {
            uint4 h, l;
            split2(a_pf[4*i+0], h.x, l.x);
            split2(a_pf[4*i+1], h.y, l.y);
            split2(a_pf[4*i+2], h.z, l.z);
            split2(a_pf[4*i+3], h.w, l.w);
            int off = ((i * 8 + wid) * 32 + lane) * 4;
            *(uint4*)(st + off)        = h;
            *(uint4*)(st + 4096 + off) = l;
        }
#pragma unroll
        for (int i = 0; i < 8; i++) {
            uint32_t h0, l0, h1, l1;
            split2(b_pf[2*i],   h0, l0);
            split2(b_pf[2*i+1], h1, l1);
            int kc = i >> 1;
            int nb = (i & 1) * 8 + wid;
            int off = 8192 + ((kc * 16 + nb) * 32 + lane) * 2;
            *(uint2*)(st + off)        = make_uint2(h0, h1);
            *(uint2*)(st + 4096 + off) = make_uint2(l0, l1);
        }
        __syncthreads();   // single barrier per iteration (double buffer)

        // ---- prefetch next tile (hidden under MMA phase) ----
        if (kb + 1 < KD / 32) {
            size_t ka = (size_t)(kb + 1) * 32;
#pragma unroll
            for (int i = 0; i < 4; i++) {
                size_t kk = ka + i * 8;
                a_pf[4*i+0] = ar0[kk];
                a_pf[4*i+1] = ar1[kk];
                a_pf[4*i+2] = ar0[kk + 4];
                a_pf[4*i+3] = ar1[kk + 4];
            }
#pragma unroll
            for (int i = 0; i < 8; i++) {
                int kc = i >> 1;
                const float* p = ((i & 1) ? bc1 : bc0) + (ka + kc * 8) * N;
                b_pf[2*i]   = p[0];
                b_pf[2*i+1] = p[(size_t)4 * N];
            }
        }

        const uint32_t* Ah  = st;
        const uint32_t* Alo = st + 4096;
        const uint32_t* Bh  = st + 8192;
        const uint32_t* Blo = st + 12288;

        // ---- MMA phase: 4 k8-steps, 3-pass split, vector frag loads ----
#pragma unroll
        for (int kc = 0; kc < 4; kc++) {
            uint32_t fa[4][4], fa2[4][4], fb[4][2];
#pragma unroll
            for (int mt = 0; mt < 4; mt++)
                *(uint4*)fa[mt] =
                    *(const uint4*)(Ah + ((kc * 8 + ambase + mt) * 32 + lane) * 4);
#pragma unroll
            for (int nt = 0; nt < 4; nt++)
                *(uint2*)fb[nt] =
                    *(const uint2*)(Bh + ((kc * 16 + nbbase + nt) * 32 + lane) * 2);
#pragma unroll
            for (int mt = 0; mt < 4; mt++)
#pragma unroll
                for (int nt = 0; nt < 4; nt++)
                    mma_tf32(acc[mt][nt], fa[mt], fb[nt]);
#pragma unroll
            for (int mt = 0; mt < 4; mt++)
                *(uint4*)fa2[mt] =
                    *(const uint4*)(Alo + ((kc * 8 + ambase + mt) * 32 + lane) * 4);
#pragma unroll
            for (int mt = 0; mt < 4; mt++)
#pragma unroll
                for (int nt = 0; nt < 4; nt++)
                    mma_tf32(acc[mt][nt], fa2[mt], fb[nt]);
#pragma unroll
            for (int nt = 0; nt < 4; nt++)
                *(uint2*)fb[nt] =
                    *(const uint2*)(Blo + ((kc * 16 + nbbase + nt) * 32 + lane) * 2);
#pragma unroll
            for (int mt = 0; mt < 4; mt++)
#pragma unroll
                for (int nt = 0; nt < 4; nt++)
                    mma_tf32(acc[mt][nt], fa[mt], fb[nt]);
        }
    }

    // ---- epilogue ----
#pragma unroll
    for (int nt = 0; nt < 4; nt++) {
        int col = bn + wn + nt * 8 + 2 * tig;
        float b0 = bias[col], b1 = bias[col + 1];
#pragma unroll
        for (int mt = 0; mt < 4; mt++) {
            int row = bm + wm + mt * 16 + gid;
            float v0 = acc[mt][nt][0] + b0;
            float v1 = acc[mt][nt][1] + b1;
            float v2 = acc[mt][nt][2] + b0;
            float v3 = acc[mt][nt][3] + b1;
            if (do_relu) {
                v0 = fmaxf(v0, 0.f); v1 = fmaxf(v1, 0.f);
                v2 = fmaxf(v2, 0.f); v3 = fmaxf(v3, 0.f);
            }
            *(float2*)(C + (size_t)row * N + col)       = make_float2(v0, v1);
            *(float2*)(C + (size_t)(row + 8) * N + col) = make_float2(v2, v3);
        }
    }
}

// ---------------- logits: warp-per-token, z-batched (5 slots) ------------------
__global__ __launch_bounds__(128) void logits_b(LogitsBatch lb)
{
    __shared__ float wt[NE][257];
    const int z = blockIdx.z;
    const float* __restrict__ X    = lb.X[z];
    const float* __restrict__ W    = lb.W[z];
    const float* __restrict__ bias = lb.bias[z];
    float* __restrict__ out        = lb.out[z];
    const int Kd = lb.Kd[z];

    const int tid = threadIdx.x;
    const int wid = tid >> 5;
    const int lane = tid & 31;
    const int tok = blockIdx.x * 4 + wid;

    float acc[NE];
#pragma unroll
    for (int e = 0; e < NE; e++) acc[e] = 0.f;

    const float* xrow = X + (size_t)tok * Kd;

    for (int c = 0; c < Kd; c += 256) {
#pragma unroll
        for (int l = 0; l < 8; l++) {
            int id = tid + l * 128;
            int k  = id >> 2;
            int e4 = (id & 3) << 2;
            float4 v = *(const float4*)(W + (size_t)(c + k) * NE + e4);
            wt[e4 + 0][k] = v.x;
            wt[e4 + 1][k] = v.y;
            wt[e4 + 2][k] = v.z;
            wt[e4 + 3][k] = v.w;
        }
        __syncthreads();
#pragma unroll
        for (int i = 0; i < 8; i++) {
            int kk = i * 32 + lane;
            float xv = xrow[c + kk];
#pragma unroll
            for (int e = 0; e < NE; e++)
                acc[e] = fmaf(xv, wt[e][kk], acc[e]);
        }
        __syncthreads();
    }
#pragma unroll
    for (int off = 16; off > 0; off >>= 1)
#pragma unroll
        for (int e = 0; e < NE; e++)
            acc[e] += __shfl_xor_sync(0xffffffffu, acc[e], off);
    if (lane == 0) {
#pragma unroll
        for (int e = 0; e < NE; e++)
            out[(size_t)tok * NE + e] = acc[e] + bias[e];
    }
}

// ---------------- router --------------------------------------------------------
__global__ __launch_bounds__(256) void router_kernel(
    const float* __restrict__ glog, const float* __restrict__ slog,
    float* __restrict__ out, float* __restrict__ partial)
{
    __shared__ float sh[256][NE];
    const int tid = threadIdx.x;
    const int tok = blockIdx.x * 256 + tid;

    float probs[NE];
    {
        float g[NE];
#pragma unroll
        for (int i = 0; i < NE; i++) g[i] = glog[(size_t)tok * NE + i];
        float mx = g[0];
#pragma unroll
        for (int i = 1; i < NE; i++) mx = fmaxf(mx, g[i]);
        float s = 0.f;
#pragma unroll
        for (int i = 0; i < NE; i++) { g[i] = expf(g[i] - mx); s += g[i]; }
        float inv = 0.7f / s;
#pragma unroll
        for (int i = 0; i < NE; i++) probs[i] = g[i] * inv;
    }
#pragma unroll
    for (int m = 0; m < NMOD; m++) {
        float g[NE];
#pragma unroll
        for (int i = 0; i < NE; i++)
            g[i] = slog[((size_t)m * TOKENS + tok) * NE + i];
        float mx = g[0];
#pragma unroll
        for (int i = 1; i < NE; i++) mx = fmaxf(mx, g[i]);
        float s = 0.f;
#pragma unroll
        for (int i = 0; i < NE; i++) { g[i] = expf(g[i] - mx); s += g[i]; }
        float inv = 0.15f / s;
#pragma unroll
        for (int i = 0; i < NE; i++) probs[i] += g[i] * inv;
    }

#pragma unroll
    for (int i = 0; i < NE; i++)
        out[RP_OFF + (size_t)tok * NE + i] = probs[i];

    unsigned used = 0;
    int idx[4]; float val[4]; float vsum = 0.f;
#pragma unroll
    for (int k = 0; k < 4; k++) {
        float best = -1.f; int bi = 0;
#pragma unroll
        for (int i = 0; i < NE; i++) {
            bool ok = !((used >> i) & 1u);
            if (ok && probs[i] > best) { best = probs[i]; bi = i; }
        }
        used |= (1u << bi);
        idx[k] = bi; val[k] = best; vsum += best;
    }
    float invv = 1.f / vsum;
#pragma unroll
    for (int k = 0; k < 4; k++) {
        size_t base = ((size_t)tok * NE + idx[k]) * CAP;
        out[base]         = 1.f;
        out[C_OFF + base] = val[k] * invv;
    }

#pragma unroll
    for (int i = 0; i < NE; i++) sh[tid][i] = probs[i];
    __syncthreads();
    if (tid < NE) {
        float s = 0.f;
        for (int i = 0; i < 256; i++) s += sh[i][tid];
        partial[blockIdx.x * NE + tid] = s;
    }
}

// ---------------- aux loss ------------------------------------------------------
__global__ void aux_kernel(const float* __restrict__ partial, float* __restrict__ out)
{
    const int tid = threadIdx.x;
    float v = 0.f;
    if (tid < NE) {
        float s = 0.f;
#pragma unroll
        for (int b = 0; b < 8; b++) s += partial[b * NE + tid];
        float mp = s * (1.f / (float)TOKENS);
        v = mp * logf(mp * (float)NE + 1e-9f);
    }
#pragma unroll
    for (int off = 16; off > 0; off >>= 1)
        v += __shfl_down_sync(0xffffffffu, v, off);
    if (tid == 0) out[AUX_OFF] = v;
}

// ---------------- launch --------------------------------------------------------
extern "C" void kernel_launch(void* const* d_in, const int* in_sizes, int n_in,
                              void* d_out, int out_size)
{
    const float* hs   = (const float*)d_in[0];
    const float* mimg = (const float*)d_in[1];
    const float* mgen = (const float*)d_in[2];
    const float* Wg1  = (const float*)d_in[3];
    const float* bg1  = (const float*)d_in[4];
    const float* Wg2  = (const float*)d_in[5];
    const float* bg2  = (const float*)d_in[6];
    const float* Wm1  = (const float*)d_in[7];
    const float* bm1  = (const float*)d_in[8];
    const float* Wm2  = (const float*)d_in[9];
    const float* bm2  = (const float*)d_in[10];
    const float* Ws1  = (const float*)d_in[11];
    const float* bs1  = (const float*)d_in[12];
    const float* Ws2  = (const float*)d_in[13];
    const float* bs2  = (const float*)d_in[14];
    float* out = (float*)d_out;

    float *T1, *T1g, *T2, *S1, *glog, *slog, *partial;
    cudaGetSymbolAddress((void**)&T1,      g_T1);
    cudaGetSymbolAddress((void**)&T1g,     g_T1g);
    cudaGetSymbolAddress((void**)&T2,      g_T2);
    cudaGetSymbolAddress((void**)&S1,      g_S1);
    cudaGetSymbolAddress((void**)&glog,    g_glog);
    cudaGetSymbolAddress((void**)&slog,    g_slog);
    cudaGetSymbolAddress((void**)&partial, g_partial);

    cudaFuncSetAttribute(gemm_hmma_b,
                         cudaFuncAttributeMaxDynamicSharedMemorySize, SMEM_BYTES);

    zero_kernel<<<4096, 256>>>((float4*)out, (int)(2 * C_OFF / 4));

    // 1. fused big GEMMs sharing A=hs: z=0 -> T1 (Wm1), z=1 -> T1g (Wg1)
    {
        GemmBatch gb{};
        gb.A[0] = hs;  gb.B[0] = Wm1; gb.bias[0] = bm1; gb.C[0] = T1;
        gb.A[1] = hs;  gb.B[1] = Wg1; gb.bias[1] = bg1; gb.C[1] = T1g;
        dim3 grid(16, 16, 2);
        gemm_hmma_b<<<grid, 256, SMEM_BYTES>>>(gb, HDIM, 1);
    }

    // 2. GEMM2: T2 = T1 @ Wm2 + bm2 (no relu)
    {
        GemmBatch gb{};
        gb.A[0] = T1; gb.B[0] = Wm2; gb.bias[0] = bm2; gb.C[0] = T2;
        dim3 grid(16, 16, 1);
        gemm_hmma_b<<<grid, 256, SMEM_BYTES>>>(gb, HDIM, 0);
    }

    // 3. fused mid GEMMs: S1[m] = relu(data_m @ Ws1_m + bs1_m)
    {
        GemmBatch gb{};
        const float* data[4] = { mimg, mgen, T2, T2 };
        for (int m = 0; m < 4; m++) {
            gb.A[m]    = data[m];
            gb.B[m]    = Ws1 + (size_t)m * HDIM * H2DIM;
            gb.bias[m] = bs1 + (size_t)m * H2DIM;
            gb.C[m]    = S1 + (size_t)m * TOKENS * H2DIM;
        }
        dim3 grid(8, 16, 4);
        gemm_hmma_b<<<grid, 256, SMEM_BYTES>>>(gb, H2DIM, 1);
    }

    // 4. all 5 logits GEMMs in one launch
    {
        LogitsBatch lb{};
        lb.X[0] = T1g; lb.W[0] = Wg2; lb.bias[0] = bg2; lb.out[0] = glog;
        lb.Kd[0] = HDIM;
        for (int m = 0; m < 4; m++) {
            lb.X[m+1]    = S1 + (size_t)m * TOKENS * H2DIM;
            lb.W[m+1]    = Ws2 + (size_t)m * H2DIM * NE;
            lb.bias[m+1] = bs2 + (size_t)m * NE;
            lb.out[m+1]  = slog + (size_t)m * TOKENS * NE;
            lb.Kd[m+1]   = H2DIM;
        }
        dim3 grid(512, 1, 5);
        logits_b<<<grid, 128>>>(lb);
    }

    router_kernel<<<8, 256>>>(glog, slog, out, partial);
    aux_kernel<<<1, 32>>>(partial, out);
}

// round 9
// speedup vs baseline: 1.0936x; 1.0936x over previous
#include <cuda_runtime.h>
#include <math.h>
#include <stdint.h>

#define TOKENS 2048
#define HDIM   2048
#define H2DIM  1024
#define NE     16
#define NMOD   4
#define CAP    768
#define KD     2048

static constexpr long long C_OFF   = (long long)TOKENS * NE * CAP;
static constexpr long long RP_OFF  = 2 * C_OFF;
static constexpr long long AUX_OFF = RP_OFF + (long long)TOKENS * NE;

// ---------------- device scratch ---------------------------------------------
__device__ float g_T1 [TOKENS * HDIM];
__device__ float g_T1g[TOKENS * HDIM];
__device__ float g_T2 [TOKENS * HDIM];
__device__ float g_S1 [NMOD * TOKENS * H2DIM];
__device__ float g_glog[TOKENS * NE];
__device__ float g_slog[NMOD * TOKENS * NE];
__device__ float g_partial[8 * NE];

struct GemmBatch {
    const float* A[4];
    const float* B[4];
    const float* bias[4];
    float*       C[4];
};
struct LogitsBatch {
    const float* X[5];
    const float* W[5];
    const float* bias[5];
    float*       out[5];
    int          Kd[5];
};

// ---------------- helpers ------------------------------------------------------
__device__ __forceinline__ void split2(float v, uint32_t& hb, uint32_t& lb) {
    asm("cvt.rna.tf32.f32 %0, %1;" : "=r"(hb) : "f"(v));
    float lo = v - __uint_as_float(hb);
    asm("cvt.rna.tf32.f32 %0, %1;" : "=r"(lb) : "f"(lo));
}

__device__ __forceinline__ void mma_tf32(float* c, const uint32_t* a, const uint32_t* b) {
    asm volatile(
        "mma.sync.aligned.m16n8k8.row.col.f32.tf32.tf32.f32 "
        "{%0,%1,%2,%3}, {%4,%5,%6,%7}, {%8,%9}, {%0,%1,%2,%3};"
        : "+f"(c[0]), "+f"(c[1]), "+f"(c[2]), "+f"(c[3])
        : "r"(a[0]), "r"(a[1]), "r"(a[2]), "r"(a[3]), "r"(b[0]), "r"(b[1]));
}

// ---------------- zero-fill -----------------------------------------------------
__global__ void zero_kernel(float4* __restrict__ p, int n4) {
    int i = blockIdx.x * blockDim.x + threadIdx.x;
    int stride = gridDim.x * blockDim.x;
    float4 z = make_float4(0.f, 0.f, 0.f, 0.f);
    for (; i < n4; i += stride) p[i] = z;
}

// ---------------- HMMA 3xTF32 GEMM, 128x64 tile, 2 CTAs/SM ---------------------
// C[M,N] = act(A[M,2048] @ W[2048,N] + bias). 128x64 CTA tile, BK=32,
// 128 threads (4 warps, 64x32 warp tiles). In-kernel tf32 hi/lo split.
// Smem per stage (uint32 words):
//   Ah[128][36]=4608 (off 0), Al=4608 (off 4608),
//   Bh[32][72]=2304  (off 9216), Bl=2304 (off 11520).  stage = 13824 words.
// Double-buffered: 110592 B -> 2 CTAs per SM.
#define STG_W  13824
#define SMEM_BYTES (2 * STG_W * 4)   // 110592

__global__ __launch_bounds__(128, 2) void gemm_hmma_b(
    GemmBatch gb, int N, int do_relu)
{
    extern __shared__ uint32_t sm[];

    const int z    = blockIdx.z;
    const float* __restrict__ A    = gb.A[z];
    const float* __restrict__ W    = gb.B[z];
    const float* __restrict__ bias = gb.bias[z];
    float* __restrict__ C          = gb.C[z];

    const int tid  = threadIdx.x;
    const int wid  = tid >> 5;
    const int lane = tid & 31;
    const int gid  = lane >> 2;
    const int tig  = lane & 3;
    const int wm   = (wid & 1) * 64;
    const int wn   = (wid >> 1) * 32;
    const int bm   = blockIdx.y * 128;
    const int bn   = blockIdx.x * 64;

    // global load mapping
    const int arow = tid >> 2;           // 0..31 ; +32*l
    const int acol = (tid & 3) * 8;      // 0,8,16,24
    const int bkr  = tid >> 4;           // 0..7  ; +8*l
    const int bcol = (tid & 15) * 4;     // 0..60

    float acc[4][4][4];
#pragma unroll
    for (int mt = 0; mt < 4; mt++)
#pragma unroll
        for (int nt = 0; nt < 4; nt++)
#pragma unroll
            for (int r = 0; r < 4; r++) acc[mt][nt][r] = 0.f;

    float4 av[8], bv[4];
    // preload kb = 0
#pragma unroll
    for (int l = 0; l < 4; l++) {
        const float* ap = A + (size_t)(bm + arow + 32 * l) * KD + acol;
        av[2 * l]     = *(const float4*)(ap);
        av[2 * l + 1] = *(const float4*)(ap + 4);
    }
#pragma unroll
    for (int l = 0; l < 4; l++)
        bv[l] = *(const float4*)(W + (size_t)(bkr + 8 * l) * N + bn + bcol);

    for (int kb = 0; kb < KD / 32; kb++) {
        uint32_t* st = sm + (kb & 1) * STG_W;
        uint32_t* Ah = st;
        uint32_t* Al = st + 4608;
        uint32_t* Bh = st + 9216;
        uint32_t* Bl = st + 11520;

        // ---- split + store current tile (conflict-free STS.128) ----
#pragma unroll
        for (int l = 0; l < 4; l++) {
            uint4 h0, l0, h1, l1;
            split2(av[2*l].x, h0.x, l0.x); split2(av[2*l].y, h0.y, l0.y);
            split2(av[2*l].z, h0.z, l0.z); split2(av[2*l].w, h0.w, l0.w);
            split2(av[2*l+1].x, h1.x, l1.x); split2(av[2*l+1].y, h1.y, l1.y);
            split2(av[2*l+1].z, h1.z, l1.z); split2(av[2*l+1].w, h1.w, l1.w);
            int off = (arow + 32 * l) * 36 + acol;
            *(uint4*)(Ah + off)     = h0;
            *(uint4*)(Ah + off + 4) = h1;
            *(uint4*)(Al + off)     = l0;
            *(uint4*)(Al + off + 4) = l1;
        }
#pragma unroll
        for (int l = 0; l < 4; l++) {
            uint4 h, lo;
            split2(bv[l].x, h.x, lo.x); split2(bv[l].y, h.y, lo.y);
            split2(bv[l].z, h.z, lo.z); split2(bv[l].w, h.w, lo.w);
            int off = (bkr + 8 * l) * 72 + bcol;
            *(uint4*)(Bh + off) = h;
            *(uint4*)(Bl + off) = lo;
        }
        __syncthreads();   // single barrier per iteration (double buffer)

        // ---- prefetch next tile (hidden under MMA phase) ----
        if (kb + 1 < KD / 32) {
            size_t ka = (size_t)(kb + 1) * 32;
#pragma unroll
            for (int l = 0; l < 4; l++) {
                const float* ap = A + (size_t)(bm + arow + 32 * l) * KD + ka + acol;
                av[2 * l]     = *(const float4*)(ap);
                av[2 * l + 1] = *(const float4*)(ap + 4);
            }
#pragma unroll
            for (int l = 0; l < 4; l++)
                bv[l] = *(const float4*)(W + (ka + bkr + 8 * l) * N + bn + bcol);
        }

        // ---- MMA phase: 4 k8-steps, 3-pass tf32 split ----
#pragma unroll
        for (int k0 = 0; k0 < 32; k0 += 8) {
            uint32_t fa[4][4], fa2[4][4], fb[4][2];
#pragma unroll
            for (int mt = 0; mt < 4; mt++) {
                int rbase = (wm + mt * 16 + gid) * 36 + k0 + tig;
                fa[mt][0] = Ah[rbase];
                fa[mt][1] = Ah[rbase + 8 * 36];
                fa[mt][2] = Ah[rbase + 4];
                fa[mt][3] = Ah[rbase + 8 * 36 + 4];
            }
#pragma unroll
            for (int nt = 0; nt < 4; nt++) {
                int cbase = (k0 + tig) * 72 + wn + nt * 8 + gid;
                fb[nt][0] = Bh[cbase];
                fb[nt][1] = Bh[cbase + 4 * 72];
            }
#pragma unroll
            for (int mt = 0; mt < 4; mt++)
#pragma unroll
                for (int nt = 0; nt < 4; nt++)
                    mma_tf32(acc[mt][nt], fa[mt], fb[nt]);
#pragma unroll
            for (int mt = 0; mt < 4; mt++) {
                int rbase = (wm + mt * 16 + gid) * 36 + k0 + tig;
                fa2[mt][0] = Al[rbase];
                fa2[mt][1] = Al[rbase + 8 * 36];
                fa2[mt][2] = Al[rbase + 4];
                fa2[mt][3] = Al[rbase + 8 * 36 + 4];
            }
#pragma unroll
            for (int mt = 0; mt < 4; mt++)
#pragma unroll
                for (int nt = 0; nt < 4; nt++)
                    mma_tf32(acc[mt][nt], fa2[mt], fb[nt]);
#pragma unroll
            for (int nt = 0; nt < 4; nt++) {
                int cbase = (k0 + tig) * 72 + wn + nt * 8 + gid;
                fb[nt][0] = Bl[cbase];
                fb[nt][1] = Bl[cbase + 4 * 72];
            }
#pragma unroll
            for (int mt = 0; mt < 4; mt++)
#pragma unroll
                for (int nt = 0; nt < 4; nt++)
                    mma_tf32(acc[mt][nt], fa[mt], fb[nt]);
        }
    }

    // ---- epilogue ----
#pragma unroll
    for (int nt = 0; nt < 4; nt++) {
        int col = bn + wn + nt * 8 + 2 * tig;
        float b0 = bias[col], b1 = bias[col + 1];
#pragma unroll
        for (int mt = 0; mt < 4; mt++) {
            int row = bm + wm + mt * 16 + gid;
            float v0 = acc[mt][nt][0] + b0;
            float v1 = acc[mt][nt][1] + b1;
            float v2 = acc[mt][nt][2] + b0;
            float v3 = acc[mt][nt][3] + b1;
            if (do_relu) {
                v0 = fmaxf(v0, 0.f); v1 = fmaxf(v1, 0.f);
                v2 = fmaxf(v2, 0.f); v3 = fmaxf(v3, 0.f);
            }
            *(float2*)(C + (size_t)row * N + col)       = make_float2(v0, v1);
            *(float2*)(C + (size_t)(row + 8) * N + col) = make_float2(v2, v3);
        }
    }
}

// ---------------- logits: warp-per-token, z-batched (5 slots) ------------------
__global__ __launch_bounds__(128) void logits_b(LogitsBatch lb)
{
    __shared__ float wt[NE][257];
    const int z = blockIdx.z;
    const float* __restrict__ X    = lb.X[z];
    const float* __restrict__ W    = lb.W[z];
    const float* __restrict__ bias = lb.bias[z];
    float* __restrict__ out        = lb.out[z];
    const int Kd = lb.Kd[z];

    const int tid = threadIdx.x;
    const int wid = tid >> 5;
    const int lane = tid & 31;
    const int tok = blockIdx.x * 4 + wid;

    float acc[NE];
#pragma unroll
    for (int e = 0; e < NE; e++) acc[e] = 0.f;

    const float* xrow = X + (size_t)tok * Kd;

    for (int c = 0; c < Kd; c += 256) {
#pragma unroll
        for (int l = 0; l < 8; l++) {
            int id = tid + l * 128;
            int k  = id >> 2;
            int e4 = (id & 3) << 2;
            float4 v = *(const float4*)(W + (size_t)(c + k) * NE + e4);
            wt[e4 + 0][k] = v.x;
            wt[e4 + 1][k] = v.y;
            wt[e4 + 2][k] = v.z;
            wt[e4 + 3][k] = v.w;
        }
        __syncthreads();
#pragma unroll
        for (int i = 0; i < 8; i++) {
            int kk = i * 32 + lane;
            float xv = xrow[c + kk];
#pragma unroll
            for (int e = 0; e < NE; e++)
                acc[e] = fmaf(xv, wt[e][kk], acc[e]);
        }
        __syncthreads();
    }
#pragma unroll
    for (int off = 16; off > 0; off >>= 1)
#pragma unroll
        for (int e = 0; e < NE; e++)
            acc[e] += __shfl_xor_sync(0xffffffffu, acc[e], off);
    if (lane == 0) {
#pragma unroll
        for (int e = 0; e < NE; e++)
            out[(size_t)tok * NE + e] = acc[e] + bias[e];
    }
}

// ---------------- router --------------------------------------------------------
__global__ __launch_bounds__(256) void router_kernel(
    const float* __restrict__ glog, const float* __restrict__ slog,
    float* __restrict__ out, float* __restrict__ partial)
{
    __shared__ float sh[256][NE];
    const int tid = threadIdx.x;
    const int tok = blockIdx.x * 256 + tid;

    float probs[NE];
    {
        float g[NE];
#pragma unroll
        for (int i = 0; i < NE; i++) g[i] = glog[(size_t)tok * NE + i];
        float mx = g[0];
#pragma unroll
        for (int i = 1; i < NE; i++) mx = fmaxf(mx, g[i]);
        float s = 0.f;
#pragma unroll
        for (int i = 0; i < NE; i++) { g[i] = expf(g[i] - mx); s += g[i]; }
        float inv = 0.7f / s;
#pragma unroll
        for (int i = 0; i < NE; i++) probs[i] = g[i] * inv;
    }
#pragma unroll
    for (int m = 0; m < NMOD; m++) {
        float g[NE];
#pragma unroll
        for (int i = 0; i < NE; i++)
            g[i] = slog[((size_t)m * TOKENS + tok) * NE + i];
        float mx = g[0];
#pragma unroll
        for (int i = 1; i < NE; i++) mx = fmaxf(mx, g[i]);
        float s = 0.f;
#pragma unroll
        for (int i = 0; i < NE; i++) { g[i] = expf(g[i] - mx); s += g[i]; }
        float inv = 0.15f / s;
#pragma unroll
        for (int i = 0; i < NE; i++) probs[i] += g[i] * inv;
    }

#pragma unroll
    for (int i = 0; i < NE; i++)
        out[RP_OFF + (size_t)tok * NE + i] = probs[i];

    unsigned used = 0;
    int idx[4]; float val[4]; float vsum = 0.f;
#pragma unroll
    for (int k = 0; k < 4; k++) {
        float best = -1.f; int bi = 0;
#pragma unroll
        for (int i = 0; i < NE; i++) {
            bool ok = !((used >> i) & 1u);
            if (ok && probs[i] > best) { best = probs[i]; bi = i; }
        }
        used |= (1u << bi);
        idx[k] = bi; val[k] = best; vsum += best;
    }
    float invv = 1.f / vsum;
#pragma unroll
    for (int k = 0; k < 4; k++) {
        size_t base = ((size_t)tok * NE + idx[k]) * CAP;
        out[base]         = 1.f;
        out[C_OFF + base] = val[k] * invv;
    }

#pragma unroll
    for (int i = 0; i < NE; i++) sh[tid][i] = probs[i];
    __syncthreads();
    if (tid < NE) {
        float s = 0.f;
        for (int i = 0; i < 256; i++) s += sh[i][tid];
        partial[blockIdx.x * NE + tid] = s;
    }
}

// ---------------- aux loss ------------------------------------------------------
__global__ void aux_kernel(const float* __restrict__ partial, float* __restrict__ out)
{
    const int tid = threadIdx.x;
    float v = 0.f;
    if (tid < NE) {
        float s = 0.f;
#pragma unroll
        for (int b = 0; b < 8; b++) s += partial[b * NE + tid];
        float mp = s * (1.f / (float)TOKENS);
        v = mp * logf(mp * (float)NE + 1e-9f);
    }
#pragma unroll
    for (int off = 16; off > 0; off >>= 1)
        v += __shfl_down_sync(0xffffffffu, v, off);
    if (tid == 0) out[AUX_OFF] = v;
}

// ---------------- launch --------------------------------------------------------
extern "C" void kernel_launch(void* const* d_in, const int* in_sizes, int n_in,
                              void* d_out, int out_size)
{
    const float* hs   = (const float*)d_in[0];
    const float* mimg = (const float*)d_in[1];
    const float* mgen = (const float*)d_in[2];
    const float* Wg1  = (const float*)d_in[3];
    const float* bg1  = (const float*)d_in[4];
    const float* Wg2  = (const float*)d_in[5];
    const float* bg2  = (const float*)d_in[6];
    const float* Wm1  = (const float*)d_in[7];
    const float* bm1  = (const float*)d_in[8];
    const float* Wm2  = (const float*)d_in[9];
    const float* bm2  = (const float*)d_in[10];
    const float* Ws1  = (const float*)d_in[11];
    const float* bs1  = (const float*)d_in[12];
    const float* Ws2  = (const float*)d_in[13];
    const float* bs2  = (const float*)d_in[14];
    float* out = (float*)d_out;

    float *T1, *T1g, *T2, *S1, *glog, *slog, *partial;
    cudaGetSymbolAddress((void**)&T1,      g_T1);
    cudaGetSymbolAddress((void**)&T1g,     g_T1g);
    cudaGetSymbolAddress((void**)&T2,      g_T2);
    cudaGetSymbolAddress((void**)&S1,      g_S1);
    cudaGetSymbolAddress((void**)&glog,    g_glog);
    cudaGetSymbolAddress((void**)&slog,    g_slog);
    cudaGetSymbolAddress((void**)&partial, g_partial);

    cudaFuncSetAttribute(gemm_hmma_b,
                         cudaFuncAttributeMaxDynamicSharedMemorySize, SMEM_BYTES);

    zero_kernel<<<4096, 256>>>((float4*)out, (int)(2 * C_OFF / 4));

    // 1. fused big GEMMs sharing A=hs: z=0 -> T1 (Wm1), z=1 -> T1g (Wg1)
    {
        GemmBatch gb{};
        gb.A[0] = hs;  gb.B[0] = Wm1; gb.bias[0] = bm1; gb.C[0] = T1;
        gb.A[1] = hs;  gb.B[1] = Wg1; gb.bias[1] = bg1; gb.C[1] = T1g;
        dim3 grid(32, 16, 2);
        gemm_hmma_b<<<grid, 128, SMEM_BYTES>>>(gb, HDIM, 1);
    }

    // 2. GEMM2: T2 = T1 @ Wm2 + bm2 (no relu)
    {
        GemmBatch gb{};
        gb.A[0] = T1; gb.B[0] = Wm2; gb.bias[0] = bm2; gb.C[0] = T2;
        dim3 grid(32, 16, 1);
        gemm_hmma_b<<<grid, 128, SMEM_BYTES>>>(gb, HDIM, 0);
    }

    // 3. fused mid GEMMs: S1[m] = relu(data_m @ Ws1_m + bs1_m)
    {
        GemmBatch gb{};
        const float* data[4] = { mimg, mgen, T2, T2 };
        for (int m = 0; m < 4; m++) {
            gb.A[m]    = data[m];
            gb.B[m]    = Ws1 + (size_t)m * HDIM * H2DIM;
            gb.bias[m] = bs1 + (size_t)m * H2DIM;
            gb.C[m]    = S1 + (size_t)m * TOKENS * H2DIM;
        }
        dim3 grid(16, 16, 4);
        gemm_hmma_b<<<grid, 128, SMEM_BYTES>>>(gb, H2DIM, 1);
    }

    // 4. all 5 logits GEMMs in one launch
    {
        LogitsBatch lb{};
        lb.X[0] = T1g; lb.W[0] = Wg2; lb.bias[0] = bg2; lb.out[0] = glog;
        lb.Kd[0] = HDIM;
        for (int m = 0; m < 4; m++) {
            lb.X[m+1]    = S1 + (size_t)m * TOKENS * H2DIM;
            lb.W[m+1]    = Ws2 + (size_t)m * H2DIM * NE;
            lb.bias[m+1] = bs2 + (size_t)m * NE;
            lb.out[m+1]  = slog + (size_t)m * TOKENS * NE;
            lb.Kd[m+1]   = H2DIM;
        }
        dim3 grid(512, 1, 5);
        logits_b<<<grid, 128>>>(lb);
    }

    router_kernel<<<8, 256>>>(glog, slog, out, partial);
    aux_kernel<<<1, 32>>>(partial, out);
}

// round 11
// speedup vs baseline: 1.1171x; 1.0215x over previous
#include <cuda_runtime.h>
#include <math.h>
#include <stdint.h>

#define TOKENS 2048
#define HDIM   2048
#define H2DIM  1024
#define NE     16
#define NMOD   4
#define CAP    768
#define KD     2048

static constexpr long long C_OFF   = (long long)TOKENS * NE * CAP;
static constexpr long long RP_OFF  = 2 * C_OFF;
static constexpr long long AUX_OFF = RP_OFF + (long long)TOKENS * NE;

// ---------------- device scratch ---------------------------------------------
__device__ float g_T1 [TOKENS * HDIM];
__device__ float g_T1g[TOKENS * HDIM];
__device__ float g_T2 [TOKENS * HDIM];
__device__ float g_S1 [NMOD * TOKENS * H2DIM];
__device__ float g_glog[TOKENS * NE];
__device__ float g_slog[NMOD * TOKENS * NE];
__device__ float g_partial[8 * NE];

struct GemmBatch {
    const float* A[4];
    const float* B[4];
    const float* bias[4];
    float*       C[4];
};
struct LogitsBatch {
    const float* X[5];
    const float* W[5];
    const float* bias[5];
    float*       out[5];
    int          Kd[5];
};

// ---------------- helpers ------------------------------------------------------
__device__ __forceinline__ void split2(float v, uint32_t& hb, uint32_t& lb) {
    asm("cvt.rna.tf32.f32 %0, %1;" : "=r"(hb) : "f"(v));
    float lo = v - __uint_as_float(hb);
    asm("cvt.rna.tf32.f32 %0, %1;" : "=r"(lb) : "f"(lo));
}

__device__ __forceinline__ void mma_tf32(float* c, const uint32_t* a, const uint32_t* b) {
    asm volatile(
        "mma.sync.aligned.m16n8k8.row.col.f32.tf32.tf32.f32 "
        "{%0,%1,%2,%3}, {%4,%5,%6,%7}, {%8,%9}, {%0,%1,%2,%3};"
        : "+f"(c[0]), "+f"(c[1]), "+f"(c[2]), "+f"(c[3])
        : "r"(a[0]), "r"(a[1]), "r"(a[2]), "r"(a[3]), "r"(b[0]), "r"(b[1]));
}

// ---------------- zero-fill -----------------------------------------------------
__global__ void zero_kernel(float4* __restrict__ p, int n4) {
    int i = blockIdx.x * blockDim.x + threadIdx.x;
    int stride = gridDim.x * blockDim.x;
    float4 z = make_float4(0.f, 0.f, 0.f, 0.f);
    for (; i < n4; i += stride) p[i] = z;
}

// ---------------- HMMA 3xTF32 GEMM, 128x64 tile, 256 thr, 2 CTAs/SM ------------
// C[M,N] = act(A[M,2048] @ W[2048,N] + bias). 128x64 CTA tile, BK=32,
// 256 threads (8 warps, 32x32 warp tiles -> 4 warps/SMSP at 2 CTAs/SM).
// Smem per stage (uint32 words):
//   Ah[128][36]=4608 (off 0), Al=4608 (off 4608),
//   Bh[32][72]=2304  (off 9216), Bl=2304 (off 11520).  stage = 13824 words.
// Double-buffered: 110592 B -> 2 CTAs per SM (221184 B <= 228K SM capacity).
#define STG_W  13824
#define SMEM_BYTES (2 * STG_W * 4)   // 110592

__global__ __launch_bounds__(256, 2) void gemm_hmma_b(
    GemmBatch gb, int N, int do_relu)
{
    extern __shared__ uint32_t sm[];

    const int z    = blockIdx.z;
    const float* __restrict__ A    = gb.A[z];
    const float* __restrict__ W    = gb.B[z];
    const float* __restrict__ bias = gb.bias[z];
    float* __restrict__ C          = gb.C[z];

    const int tid  = threadIdx.x;
    const int wid  = tid >> 5;
    const int lane = tid & 31;
    const int gid  = lane >> 2;
    const int tig  = lane & 3;
    const int wm   = (wid & 3) * 32;     // 4 m-blocks of 32 rows
    const int wn   = (wid >> 2) * 32;    // 2 n-blocks of 32 cols
    const int bm   = blockIdx.y * 128;
    const int bn   = blockIdx.x * 64;

    // global load mapping (256 threads)
    const int arow = tid >> 2;           // 0..63 ; +64*l
    const int acol = (tid & 3) * 8;      // 0,8,16,24 (2 float4 each)
    const int bkr  = tid >> 4;           // 0..15 ; +16*l
    const int bcol = (tid & 15) * 4;     // 0..60

    float acc[2][4][4];
#pragma unroll
    for (int mt = 0; mt < 2; mt++)
#pragma unroll
        for (int nt = 0; nt < 4; nt++)
#pragma unroll
            for (int r = 0; r < 4; r++) acc[mt][nt][r] = 0.f;

    float4 av[4], bv[2];
    // preload kb = 0
#pragma unroll
    for (int l = 0; l < 2; l++) {
        const float* ap = A + (size_t)(bm + arow + 64 * l) * KD + acol;
        av[2 * l]     = *(const float4*)(ap);
        av[2 * l + 1] = *(const float4*)(ap + 4);
    }
#pragma unroll
    for (int l = 0; l < 2; l++)
        bv[l] = *(const float4*)(W + (size_t)(bkr + 16 * l) * N + bn + bcol);

    for (int kb = 0; kb < KD / 32; kb++) {
        uint32_t* st = sm + (kb & 1) * STG_W;
        uint32_t* Ah = st;
        uint32_t* Al = st + 4608;
        uint32_t* Bh = st + 9216;
        uint32_t* Bl = st + 11520;

        // ---- split + store current tile (conflict-free STS.128) ----
#pragma unroll
        for (int l = 0; l < 2; l++) {
            uint4 h0, l0, h1, l1;
            split2(av[2*l].x, h0.x, l0.x); split2(av[2*l].y, h0.y, l0.y);
            split2(av[2*l].z, h0.z, l0.z); split2(av[2*l].w, h0.w, l0.w);
            split2(av[2*l+1].x, h1.x, l1.x); split2(av[2*l+1].y, h1.y, l1.y);
            split2(av[2*l+1].z, h1.z, l1.z); split2(av[2*l+1].w, h1.w, l1.w);
            int off = (arow + 64 * l) * 36 + acol;
            *(uint4*)(Ah + off)     = h0;
            *(uint4*)(Ah + off + 4) = h1;
            *(uint4*)(Al + off)     = l0;
            *(uint4*)(Al + off + 4) = l1;
        }
#pragma unroll
        for (int l = 0; l < 2; l++) {
            uint4 h, lo;
            split2(bv[l].x, h.x, lo.x); split2(bv[l].y, h.y, lo.y);
            split2(bv[l].z, h.z, lo.z); split2(bv[l].w, h.w, lo.w);
            int off = (bkr + 16 * l) * 72 + bcol;
            *(uint4*)(Bh + off) = h;
            *(uint4*)(Bl + off) = lo;
        }
        __syncthreads();   // single barrier per iteration (double buffer)

        // ---- prefetch next tile (hidden under MMA phase) ----
        if (kb + 1 < KD / 32) {
            size_t ka = (size_t)(kb + 1) * 32;
#pragma unroll
            for (int l = 0; l < 2; l++) {
                const float* ap = A + (size_t)(bm + arow + 64 * l) * KD + ka + acol;
                av[2 * l]     = *(const float4*)(ap);
                av[2 * l + 1] = *(const float4*)(ap + 4);
            }
#pragma unroll
            for (int l = 0; l < 2; l++)
                bv[l] = *(const float4*)(W + (ka + bkr + 16 * l) * N + bn + bcol);
        }

        // ---- MMA phase: 4 k8-steps, 3-pass tf32 split ----
#pragma unroll
        for (int k0 = 0; k0 < 32; k0 += 8) {
            uint32_t fa[2][4], fa2[2][4], fb[4][2];
#pragma unroll
            for (int mt = 0; mt < 2; mt++) {
                int rbase = (wm + mt * 16 + gid) * 36 + k0 + tig;
                fa[mt][0] = Ah[rbase];
                fa[mt][1] = Ah[rbase + 8 * 36];
                fa[mt][2] = Ah[rbase + 4];
                fa[mt][3] = Ah[rbase + 8 * 36 + 4];
            }
#pragma unroll
            for (int nt = 0; nt < 4; nt++) {
                int cbase = (k0 + tig) * 72 + wn + nt * 8 + gid;
                fb[nt][0] = Bh[cbase];
                fb[nt][1] = Bh[cbase + 4 * 72];
            }
#pragma unroll
            for (int mt = 0; mt < 2; mt++)
#pragma unroll
                for (int nt = 0; nt < 4; nt++)
                    mma_tf32(acc[mt][nt], fa[mt], fb[nt]);
#pragma unroll
            for (int mt = 0; mt < 2; mt++) {
                int rbase = (wm + mt * 16 + gid) * 36 + k0 + tig;
                fa2[mt][0] = Al[rbase];
                fa2[mt][1] = Al[rbase + 8 * 36];
                fa2[mt][2] = Al[rbase + 4];
                fa2[mt][3] = Al[rbase + 8 * 36 + 4];
            }
#pragma unroll
            for (int mt = 0; mt < 2; mt++)
#pragma unroll
                for (int nt = 0; nt < 4; nt++)
                    mma_tf32(acc[mt][nt], fa2[mt], fb[nt]);
#pragma unroll
            for (int nt = 0; nt < 4; nt++) {
                int cbase = (k0 + tig) * 72 + wn + nt * 8 + gid;
                fb[nt][0] = Bl[cbase];
                fb[nt][1] = Bl[cbase + 4 * 72];
            }
#pragma unroll
            for (int mt = 0; mt < 2; mt++)
#pragma unroll
                for (int nt = 0; nt < 4; nt++)
                    mma_tf32(acc[mt][nt], fa[mt], fb[nt]);
        }
    }

    // ---- epilogue ----
#pragma unroll
    for (int nt = 0; nt < 4; nt++) {
        int col = bn + wn + nt * 8 + 2 * tig;
        float b0 = bias[col], b1 = bias[col + 1];
#pragma unroll
        for (int mt = 0; mt < 2; mt++) {
            int row = bm + wm + mt * 16 + gid;
            float v0 = acc[mt][nt][0] + b0;
            float v1 = acc[mt][nt][1] + b1;
            float v2 = acc[mt][nt][2] + b0;
            float v3 = acc[mt][nt][3] + b1;
            if (do_relu) {
                v0 = fmaxf(v0, 0.f); v1 = fmaxf(v1, 0.f);
                v2 = fmaxf(v2, 0.f); v3 = fmaxf(v3, 0.f);
            }
            *(float2*)(C + (size_t)row * N + col)       = make_float2(v0, v1);
            *(float2*)(C + (size_t)(row + 8) * N + col) = make_float2(v2, v3);
        }
    }
}

// ---------------- logits: warp-per-token, z-batched (5 slots) ------------------
__global__ __launch_bounds__(128) void logits_b(LogitsBatch lb)
{
    __shared__ float wt[NE][257];
    const int z = blockIdx.z;
    const float* __restrict__ X    = lb.X[z];
    const float* __restrict__ W    = lb.W[z];
    const float* __restrict__ bias = lb.bias[z];
    float* __restrict__ out        = lb.out[z];
    const int Kd = lb.Kd[z];

    const int tid = threadIdx.x;
    const int wid = tid >> 5;
    const int lane = tid & 31;
    const int tok = blockIdx.x * 4 + wid;

    float acc[NE];
#pragma unroll
    for (int e = 0; e < NE; e++) acc[e] = 0.f;

    const float* xrow = X + (size_t)tok * Kd;

    for (int c = 0; c < Kd; c += 256) {
#pragma unroll
        for (int l = 0; l < 8; l++) {
            int id = tid + l * 128;
            int k  = id >> 2;
            int e4 = (id & 3) << 2;
            float4 v = *(const float4*)(W + (size_t)(c + k) * NE + e4);
            wt[e4 + 0][k] = v.x;
            wt[e4 + 1][k] = v.y;
            wt[e4 + 2][k] = v.z;
            wt[e4 + 3][k] = v.w;
        }
        __syncthreads();
#pragma unroll
        for (int i = 0; i < 8; i++) {
            int kk = i * 32 + lane;
            float xv = xrow[c + kk];
#pragma unroll
            for (int e = 0; e < NE; e++)
                acc[e] = fmaf(xv, wt[e][kk], acc[e]);
        }
        __syncthreads();
    }
#pragma unroll
    for (int off = 16; off > 0; off >>= 1)
#pragma unroll
        for (int e = 0; e < NE; e++)
            acc[e] += __shfl_xor_sync(0xffffffffu, acc[e], off);
    if (lane == 0) {
#pragma unroll
        for (int e = 0; e < NE; e++)
            out[(size_t)tok * NE + e] = acc[e] + bias[e];
    }
}

// ---------------- router --------------------------------------------------------
__global__ __launch_bounds__(256) void router_kernel(
    const float* __restrict__ glog, const float* __restrict__ slog,
    float* __restrict__ out, float* __restrict__ partial)
{
    __shared__ float sh[256][NE];
    const int tid = threadIdx.x;
    const int tok = blockIdx.x * 256 + tid;

    float probs[NE];
    {
        float g[NE];
#pragma unroll
        for (int i = 0; i < NE; i++) g[i] = glog[(size_t)tok * NE + i];
        float mx = g[0];
#pragma unroll
        for (int i = 1; i < NE; i++) mx = fmaxf(mx, g[i]);
        float s = 0.f;
#pragma unroll
        for (int i = 0; i < NE; i++) { g[i] = expf(g[i] - mx); s += g[i]; }
        float inv = 0.7f / s;
#pragma unroll
        for (int i = 0; i < NE; i++) probs[i] = g[i] * inv;
    }
#pragma unroll
    for (int m = 0; m < NMOD; m++) {
        float g[NE];
#pragma unroll
        for (int i = 0; i < NE; i++)
            g[i] = slog[((size_t)m * TOKENS + tok) * NE + i];
        float mx = g[0];
#pragma unroll
        for (int i = 1; i < NE; i++) mx = fmaxf(mx, g[i]);
        float s = 0.f;
#pragma unroll
        for (int i = 0; i < NE; i++) { g[i] = expf(g[i] - mx); s += g[i]; }
        float inv = 0.15f / s;
#pragma unroll
        for (int i = 0; i < NE; i++) probs[i] += g[i] * inv;
    }

#pragma unroll
    for (int i = 0; i < NE; i++)
        out[RP_OFF + (size_t)tok * NE + i] = probs[i];

    unsigned used = 0;
    int idx[4]; float val[4]; float vsum = 0.f;
#pragma unroll
    for (int k = 0; k < 4; k++) {
        float best = -1.f; int bi = 0;
#pragma unroll
        for (int i = 0; i < NE; i++) {
            bool ok = !((used >> i) & 1u);
            if (ok && probs[i] > best) { best = probs[i]; bi = i; }
        }
        used |= (1u << bi);
        idx[k] = bi; val[k] = best; vsum += best;
    }
    float invv = 1.f / vsum;
#pragma unroll
    for (int k = 0; k < 4; k++) {
        size_t base = ((size_t)tok * NE + idx[k]) * CAP;
        out[base]         = 1.f;
        out[C_OFF + base] = val[k] * invv;
    }

#pragma unroll
    for (int i = 0; i < NE; i++) sh[tid][i] = probs[i];
    __syncthreads();
    if (tid < NE) {
        float s = 0.f;
        for (int i = 0; i < 256; i++) s += sh[i][tid];
        partial[blockIdx.x * NE + tid] = s;
    }
}

// ---------------- aux loss ------------------------------------------------------
__global__ void aux_kernel(const float* __restrict__ partial, float* __restrict__ out)
{
    const int tid = threadIdx.x;
    float v = 0.f;
    if (tid < NE) {
        float s = 0.f;
#pragma unroll
        for (int b = 0; b < 8; b++) s += partial[b * NE + tid];
        float mp = s * (1.f / (float)TOKENS);
        v = mp * logf(mp * (float)NE + 1e-9f);
    }
#pragma unroll
    for (int off = 16; off > 0; off >>= 1)
        v += __shfl_down_sync(0xffffffffu, v, off);
    if (tid == 0) out[AUX_OFF] = v;
}

// ---------------- launch --------------------------------------------------------
extern "C" void kernel_launch(void* const* d_in, const int* in_sizes, int n_in,
                              void* d_out, int out_size)
{
    const float* hs   = (const float*)d_in[0];
    const float* mimg = (const float*)d_in[1];
    const float* mgen = (const float*)d_in[2];
    const float* Wg1  = (const float*)d_in[3];
    const float* bg1  = (const float*)d_in[4];
    const float* Wg2  = (const float*)d_in[5];
    const float* bg2  = (const float*)d_in[6];
    const float* Wm1  = (const float*)d_in[7];
    const float* bm1  = (const float*)d_in[8];
    const float* Wm2  = (const float*)d_in[9];
    const float* bm2  = (const float*)d_in[10];
    const float* Ws1  = (const float*)d_in[11];
    const float* bs1  = (const float*)d_in[12];
    const float* Ws2  = (const float*)d_in[13];
    const float* bs2  = (const float*)d_in[14];
    float* out = (float*)d_out;

    float *T1, *T1g, *T2, *S1, *glog, *slog, *partial;
    cudaGetSymbolAddress((void**)&T1,      g_T1);
    cudaGetSymbolAddress((void**)&T1g,     g_T1g);
    cudaGetSymbolAddress((void**)&T2,      g_T2);
    cudaGetSymbolAddress((void**)&S1,      g_S1);
    cudaGetSymbolAddress((void**)&glog,    g_glog);
    cudaGetSymbolAddress((void**)&slog,    g_slog);
    cudaGetSymbolAddress((void**)&partial, g_partial);

    cudaFuncSetAttribute(gemm_hmma_b,
                         cudaFuncAttributeMaxDynamicSharedMemorySize, SMEM_BYTES);

    zero_kernel<<<4096, 256>>>((float4*)out, (int)(2 * C_OFF / 4));

    // 1. fused big GEMMs sharing A=hs: z=0 -> T1 (Wm1), z=1 -> T1g (Wg1)
    {
        GemmBatch gb{};
        gb.A[0] = hs;  gb.B[0] = Wm1; gb.bias[0] = bm1; gb.C[0] = T1;
        gb.A[1] = hs;  gb.B[1] = Wg1; gb.bias[1] = bg1; gb.C[1] = T1g;
        dim3 grid(32, 16, 2);
        gemm_hmma_b<<<grid, 256, SMEM_BYTES>>>(gb, HDIM, 1);
    }

    // 2. GEMM2: T2 = T1 @ Wm2 + bm2 (no relu)
    {
        GemmBatch gb{};
        gb.A[0] = T1; gb.B[0] = Wm2; gb.bias[0] = bm2; gb.C[0] = T2;
        dim3 grid(32, 16, 1);
        gemm_hmma_b<<<grid, 256, SMEM_BYTES>>>(gb, HDIM, 0);
    }

    // 3. fused mid GEMMs: S1[m] = relu(data_m @ Ws1_m + bs1_m)
    {
        GemmBatch gb{};
        const float* data[4] = { mimg, mgen, T2, T2 };
        for (int m = 0; m < 4; m++) {
            gb.A[m]    = data[m];
            gb.B[m]    = Ws1 + (size_t)m * HDIM * H2DIM;
            gb.bias[m] = bs1 + (size_t)m * H2DIM;
            gb.C[m]    = S1 + (size_t)m * TOKENS * H2DIM;
        }
        dim3 grid(16, 16, 4);
        gemm_hmma_b<<<grid, 256, SMEM_BYTES>>>(gb, H2DIM, 1);
    }

    // 4. all 5 logits GEMMs in one launch
    {
        LogitsBatch lb{};
        lb.X[0] = T1g; lb.W[0] = Wg2; lb.bias[0] = bg2; lb.out[0] = glog;
        lb.Kd[0] = HDIM;
        for (int m = 0; m < 4; m++) {
            lb.X[m+1]    = S1 + (size_t)m * TOKENS * H2DIM;
            lb.W[m+1]    = Ws2 + (size_t)m * H2DIM * NE;
            lb.bias[m+1] = bs2 + (size_t)m * NE;
            lb.out[m+1]  = slog + (size_t)m * TOKENS * NE;
            lb.Kd[m+1]   = H2DIM;
        }
        dim3 grid(512, 1, 5);
        logits_b<<<grid, 128>>>(lb);
    }

    router_kernel<<<8, 256>>>(glog, slog, out, partial);
    aux_kernel<<<1, 32>>>(partial, out);
}